// round 14
// baseline (speedup 1.0000x reference)
#include <cuda_runtime.h>

#define BB    4
#define NN    8192
#define ALPHA 5.0f
#define EPS   1e-12f

#define SPLIT  128               // ref-dimension split
#define SLICE  (NN / SPLIT)      // 64 refs per block
#define QB     128               // threads per knn block
#define QPT    8                 // queries per thread (4 packed f32x2 lanes)
#define QBLK   (QB * QPT)        // 1024 queries per block
#define GX     (NN / QBLK)       // 8 query-groups per batch

#define FB     8                 // finish blocks per batch (8*1024 = NN)

typedef unsigned long long ull;
typedef unsigned int uint;

// Reversed-order float keys: min over floats == max over keys; 0 = identity.
__device__ uint  g_key [BB * NN];   // zero at load; k_dsum self-resets
__device__ float g_dsum[BB * NN];
__device__ float g_bsum[BB];        // zeroed by k_knn each launch

__device__ __forceinline__ uint rkey(float f) {
    uint b = __float_as_uint(f);
    uint u = (b & 0x80000000u) ? ~b : (b | 0x80000000u);  // ascending order
    return ~u;                                            // descending
}
__device__ __forceinline__ float unrkey(uint r) {
    uint u = ~r;
    uint b = (u & 0x80000000u) ? (u & 0x7FFFFFFFu) : ~u;
    return __uint_as_float(b);
}

__device__ __forceinline__ ull f2u(float a, float b) {
    union { float f[2]; ull u; } t; t.f[0] = a; t.f[1] = b; return t.u;
}
__device__ __forceinline__ void u2f(ull v, float& a, float& b) {
    union { float f[2]; ull u; } t; t.u = v; a = t.f[0]; b = t.f[1];
}
__device__ __forceinline__ ull fma2(ull a, ull b, ull c) {
    ull d; asm("fma.rn.f32x2 %0, %1, %2, %3;" : "=l"(d) : "l"(a), "l"(b), "l"(c)); return d;
}

// Each block: 1024 queries (8/thread, 4 packed f32x2 pairs) vs a 64-ref slice.
// Refs are PRE-PACKED in smem as broadcast pairs {x,x},{y,y} / {z,z},{w,w}
// so each LDS.128 yields two ready fma2 operands (no register MOV packing).
// Emits per-query partial min of (w_j - 2*dot_j) via one atomicMax(rkey).
// Self block (slice inside this block's query range): 2-min for all, emit
// the second-smallest only for the (k, tid-half) subset whose self is here.
__global__ void __launch_bounds__(QB, 10) k_knn(const float* __restrict__ xyz,
                                                float* __restrict__ out) {
    __shared__ ulonglong2 sXY[SLICE];   // {x,x}, {y,y} per ref
    __shared__ ulonglong2 sZW[SLICE];   // {z,z}, {w,w} per ref

    const int b     = blockIdx.y;
    const int slice = blockIdx.z;
    const int tid   = threadIdx.x;

    // per-replay resets (ordered before k_dsum/k_loss by kernel boundaries)
    if (blockIdx.x == 0 && slice == 0 && tid == 0) {
        if (b == 0) out[0] = 0.0f;
        g_bsum[b] = 0.0f;
    }

    // load + pre-pack this block's ref slice (threads 0..SLICE-1)
    if (tid < SLICE) {
        const float* __restrict__ src = xyz + (size_t)(b * NN + slice * SLICE + tid) * 3;
        float x = src[0], y = src[1], z = src[2];
        float w = (x*x + y*y) + z*z;                 // match jnp.sum order
        sXY[tid] = make_ulonglong2(f2u(x, x), f2u(y, y));
        sZW[tid] = make_ulonglong2(f2u(z, z), f2u(w, w));
    }

    // 8 queries per thread at qbase + k*QB; packed as 4 f32x2 pairs
    const int qbase = blockIdx.x * QBLK + tid;
    ull mx[4], my[4], mz[4];
    #pragma unroll
    for (int p = 0; p < 4; p++) {
        const float* qa = xyz + (size_t)(b * NN + qbase + (2*p    ) * QB) * 3;
        const float* qb = xyz + (size_t)(b * NN + qbase + (2*p + 1) * QB) * 3;
        mx[p] = f2u(-2.0f*qa[0], -2.0f*qb[0]);
        my[p] = f2u(-2.0f*qa[1], -2.0f*qb[1]);
        mz[p] = f2u(-2.0f*qa[2], -2.0f*qb[2]);
    }

    __syncthreads();

    const bool self_block = ((slice >> 4) == blockIdx.x);  // QBLK == 16*SLICE
    float part[QPT];

    if (!self_block) {
        // fast path: plain min, 8 independent accumulators
        float a[QPT];
        #pragma unroll
        for (int k = 0; k < QPT; k++) a[k] = 3.4e38f;

        #pragma unroll 4
        for (int j = 0; j < SLICE; j++) {
            ulonglong2 xy = sXY[j];
            ulonglong2 zw = sZW[j];
            #pragma unroll
            for (int p = 0; p < 4; p++) {
                ull t = fma2(mx[p], xy.x, fma2(my[p], xy.y, fma2(mz[p], zw.x, zw.y)));
                float c0, c1;
                u2f(t, c0, c1);
                a[2*p]   = fminf(a[2*p],   c0);
                a[2*p+1] = fminf(a[2*p+1], c1);
            }
        }
        #pragma unroll
        for (int k = 0; k < QPT; k++) part[k] = a[k];
    } else {
        // self path: 2-min per query; the subset with self in this slice
        // (query-group sk, tid-half th) gets the second smallest.
        float s0[QPT], s1[QPT];
        #pragma unroll
        for (int k = 0; k < QPT; k++) { s0[k] = 3.4e38f; s1[k] = 3.4e38f; }

        #pragma unroll 2
        for (int j = 0; j < SLICE; j++) {
            ulonglong2 xy = sXY[j];
            ulonglong2 zw = sZW[j];
            #pragma unroll
            for (int p = 0; p < 4; p++) {
                ull t = fma2(mx[p], xy.x, fma2(my[p], xy.y, fma2(mz[p], zw.x, zw.y)));
                float c0, c1;
                u2f(t, c0, c1);
                float h0 = fmaxf(s0[2*p], c0);
                s0[2*p] = fminf(s0[2*p], c0);
                s1[2*p] = fminf(s1[2*p], h0);
                float h1 = fmaxf(s0[2*p+1], c1);
                s0[2*p+1] = fminf(s0[2*p+1], c1);
                s1[2*p+1] = fminf(s1[2*p+1], h1);
            }
        }
        const int sp  = slice & 15;          // slice position within block range
        const int sk  = sp >> 1;             // query-group whose selves are here
        const int th  = sp & 1;              // which tid-half of that group
        const bool tm = ((tid >> 6) == th);
        #pragma unroll
        for (int k = 0; k < QPT; k++)
            part[k] = (k == sk && tm) ? s1[k] : s0[k];
    }

    #pragma unroll
    for (int k = 0; k < QPT; k++)
        atomicMax(&g_key[b * NN + qbase + k * QB], rkey(part[k]));
}

__device__ __forceinline__ float reduce1024(float v, float* sh) {
    int lane = threadIdx.x & 31, wid = threadIdx.x >> 5;
    #pragma unroll
    for (int o = 16; o; o >>= 1) v += __shfl_down_sync(0xFFFFFFFFu, v, o);
    if (lane == 0) sh[wid] = v;
    __syncthreads();
    if (wid == 0) {
        v = sh[lane];
        #pragma unroll
        for (int o = 16; o; o >>= 1) v += __shfl_down_sync(0xFFFFFFFFu, v, o);
    }
    return v;   // valid in thread 0
}

// grid (FB, BB) x 1024: one point/thread. Decode key (+reset), dsum, batch sum.
__global__ void __launch_bounds__(1024) k_dsum(const float* __restrict__ xyz) {
    __shared__ float sh[32];
    const int b = blockIdx.y;
    const int q = blockIdx.x * 1024 + threadIdx.x;
    const int i = b * NN + q;

    uint r = g_key[i];
    g_key[i] = 0;                                   // self-reset for replay
    float m = unrkey(r);

    const float* p = xyz + (size_t)i * 3;
    float px = p[0], py = p[1], pz = p[2];
    float w = (px*px + py*py) + pz*pz;
    float d2nn = w + m;                             // ||q||^2 + shifted min
    float mself = fmaf(-2.0f*px, px, fmaf(-2.0f*py, py, fmaf(-2.0f*pz, pz, w)));
    float d2self = w + mself;

    float ds = sqrtf(fmaxf(d2self, EPS)) + sqrtf(fmaxf(d2nn, EPS));
    g_dsum[i] = ds;

    float t = reduce1024(ds, sh);
    if (threadIdx.x == 0) atomicAdd(&g_bsum[b], t);
}

// grid (FB, BB) x 1024: threshold (bsum final at kernel boundary), masked sum.
__global__ void __launch_bounds__(1024) k_loss(float* __restrict__ out) {
    __shared__ float sh[32];
    const int b = blockIdx.y;
    const int i = b * NN + blockIdx.x * 1024 + threadIdx.x;

    float thr = (g_bsum[b] / (float)NN) * ALPHA;    // mean, then *ALPHA (ref order)
    float d = g_dsum[i];
    float s = (d > thr) ? d : 0.0f;
    s = reduce1024(s, sh);
    if (threadIdx.x == 0) atomicAdd(out, s);
}

extern "C" void kernel_launch(void* const* d_in, const int* in_sizes, int n_in,
                              void* d_out, int out_size) {
    const float* xyz = (const float*)d_in[0];
    float* out = (float*)d_out;

    dim3 grid(GX, BB, SPLIT);            // 8 x 4 x 128 = 4096 blocks
    k_knn<<<grid, QB>>>(xyz, out);

    dim3 fgrid(FB, BB);                  // 32 wide finish blocks
    k_dsum<<<fgrid, 1024>>>(xyz);
    k_loss<<<fgrid, 1024>>>(out);
}

// round 15
// speedup vs baseline: 1.1841x; 1.1841x over previous
#include <cuda_runtime.h>

#define BB    4
#define NN    8192
#define ALPHA 5.0f
#define EPS   1e-12f

#define SPLIT  64                // ref-dimension split (64 atomics/key max)
#define SLICE  (NN / SPLIT)      // 128 refs per block
#define QB     128               // threads per knn block
#define QPT    4                 // queries per thread (2 packed f32x2 lanes)
#define QBLK   (QB * QPT)        // 512 queries per block
#define GX     (NN / QBLK)       // 16 query-groups per batch

#define FB     8                 // finish blocks per batch (8*1024 = NN)

typedef unsigned long long ull;
typedef unsigned int uint;

// Reversed-order float keys: min over floats == max over keys; 0 = identity.
__device__ uint  g_key [BB * NN];   // zero at load; k_dsum self-resets
__device__ float g_dsum[BB * NN];
__device__ float g_bsum[BB];        // zeroed by k_knn each launch

__device__ __forceinline__ uint rkey(float f) {
    uint b = __float_as_uint(f);
    uint u = (b & 0x80000000u) ? ~b : (b | 0x80000000u);  // ascending order
    return ~u;                                            // descending
}
__device__ __forceinline__ float unrkey(uint r) {
    uint u = ~r;
    uint b = (u & 0x80000000u) ? (u & 0x7FFFFFFFu) : ~u;
    return __uint_as_float(b);
}

__device__ __forceinline__ ull f2u(float a, float b) {
    union { float f[2]; ull u; } t; t.f[0] = a; t.f[1] = b; return t.u;
}
__device__ __forceinline__ void u2f(ull v, float& a, float& b) {
    union { float f[2]; ull u; } t; t.u = v; a = t.f[0]; b = t.f[1];
}
__device__ __forceinline__ ull fma2(ull a, ull b, ull c) {
    ull d; asm("fma.rn.f32x2 %0, %1, %2, %3;" : "=l"(d) : "l"(a), "l"(b), "l"(c)); return d;
}

// Each block: 512 queries (4/thread, 2 packed f32x2 pairs) vs a 128-ref slice.
// Refs are PRE-PACKED in smem as broadcast pairs {x,x},{y,y} / {z,z},{w,w},
// so each LDS.128 yields two ready fma2 operands (no register MOV packing).
// Per window: 2 LDS + 6 fma2 + 4 FMNMX = 12 issues / 4 pair-evals.
// Emits per-query partial min of (w_j - 2*dot_j) via one atomicMax(rkey).
// Self block (slice covers query-group slice&3): 2-min, emit second smallest
// for that group (self is its strict slice min).
__global__ void __launch_bounds__(QB, 10) k_knn(const float* __restrict__ xyz,
                                                float* __restrict__ out) {
    __shared__ ulonglong2 sXY[SLICE];   // {x,x}, {y,y} per ref
    __shared__ ulonglong2 sZW[SLICE];   // {z,z}, {w,w} per ref

    const int b     = blockIdx.y;
    const int slice = blockIdx.z;
    const int tid   = threadIdx.x;

    // per-replay resets (ordered before k_dsum/k_loss by kernel boundaries)
    if (blockIdx.x == 0 && slice == 0 && tid == 0) {
        if (b == 0) out[0] = 0.0f;
        g_bsum[b] = 0.0f;
    }

    // load + pre-pack this block's ref slice (1 ref per thread; SLICE == QB)
    {
        const float* __restrict__ src = xyz + (size_t)(b * NN + slice * SLICE + tid) * 3;
        float x = src[0], y = src[1], z = src[2];
        float w = (x*x + y*y) + z*z;                 // match jnp.sum order
        sXY[tid] = make_ulonglong2(f2u(x, x), f2u(y, y));
        sZW[tid] = make_ulonglong2(f2u(z, z), f2u(w, w));
    }

    // 4 queries per thread at qbase + k*QB; packed as (q0,q1), (q2,q3)
    const int qbase = blockIdx.x * QBLK + tid;
    ull mx01, my01, mz01, mx23, my23, mz23;
    {
        const float* q0 = xyz + (size_t)(b * NN + qbase + 0 * QB) * 3;
        const float* q1 = xyz + (size_t)(b * NN + qbase + 1 * QB) * 3;
        const float* q2 = xyz + (size_t)(b * NN + qbase + 2 * QB) * 3;
        const float* q3 = xyz + (size_t)(b * NN + qbase + 3 * QB) * 3;
        mx01 = f2u(-2.0f*q0[0], -2.0f*q1[0]);
        my01 = f2u(-2.0f*q0[1], -2.0f*q1[1]);
        mz01 = f2u(-2.0f*q0[2], -2.0f*q1[2]);
        mx23 = f2u(-2.0f*q2[0], -2.0f*q3[0]);
        my23 = f2u(-2.0f*q2[1], -2.0f*q3[1]);
        mz23 = f2u(-2.0f*q2[2], -2.0f*q3[2]);
    }

    __syncthreads();

    const bool self_block = ((slice >> 2) == blockIdx.x);  // QBLK == 4*SLICE
    float part[QPT];

    if (!self_block) {
        // fast path: plain min, 4 independent accumulators
        float a0 = 3.4e38f, a1 = 3.4e38f, a2 = 3.4e38f, a3 = 3.4e38f;

        #pragma unroll 4
        for (int j = 0; j < SLICE; j++) {
            ulonglong2 xy = sXY[j];
            ulonglong2 zw = sZW[j];
            ull t01 = fma2(mx01, xy.x, fma2(my01, xy.y, fma2(mz01, zw.x, zw.y)));
            ull t23 = fma2(mx23, xy.x, fma2(my23, xy.y, fma2(mz23, zw.x, zw.y)));
            float c0, c1, c2, c3;
            u2f(t01, c0, c1); u2f(t23, c2, c3);
            a0 = fminf(a0, c0);
            a1 = fminf(a1, c1);
            a2 = fminf(a2, c2);
            a3 = fminf(a3, c3);
        }
        part[0] = a0; part[1] = a1; part[2] = a2; part[3] = a3;
    } else {
        // self path: 2-min per query; group (slice&3) gets second smallest
        float s0[QPT], s1[QPT];
        #pragma unroll
        for (int k = 0; k < QPT; k++) { s0[k] = 3.4e38f; s1[k] = 3.4e38f; }

        #pragma unroll 2
        for (int j = 0; j < SLICE; j++) {
            ulonglong2 xy = sXY[j];
            ulonglong2 zw = sZW[j];
            ull t01 = fma2(mx01, xy.x, fma2(my01, xy.y, fma2(mz01, zw.x, zw.y)));
            ull t23 = fma2(mx23, xy.x, fma2(my23, xy.y, fma2(mz23, zw.x, zw.y)));
            float c[QPT];
            u2f(t01, c[0], c[1]); u2f(t23, c[2], c[3]);
            #pragma unroll
            for (int k = 0; k < QPT; k++) {
                float hi = fmaxf(s0[k], c[k]);
                s0[k] = fminf(s0[k], c[k]);
                s1[k] = fminf(s1[k], hi);
            }
        }
        const int special = slice & 3;               // group whose selves are here
        #pragma unroll
        for (int k = 0; k < QPT; k++)
            part[k] = (k == special) ? s1[k] : s0[k];
    }

    #pragma unroll
    for (int k = 0; k < QPT; k++)
        atomicMax(&g_key[b * NN + qbase + k * QB], rkey(part[k]));
}

__device__ __forceinline__ float reduce1024(float v, float* sh) {
    int lane = threadIdx.x & 31, wid = threadIdx.x >> 5;
    #pragma unroll
    for (int o = 16; o; o >>= 1) v += __shfl_down_sync(0xFFFFFFFFu, v, o);
    if (lane == 0) sh[wid] = v;
    __syncthreads();
    if (wid == 0) {
        v = sh[lane];
        #pragma unroll
        for (int o = 16; o; o >>= 1) v += __shfl_down_sync(0xFFFFFFFFu, v, o);
    }
    return v;   // valid in thread 0
}

// grid (FB, BB) x 1024: one point/thread. Decode key (+reset), dsum, batch sum.
__global__ void __launch_bounds__(1024) k_dsum(const float* __restrict__ xyz) {
    __shared__ float sh[32];
    const int b = blockIdx.y;
    const int q = blockIdx.x * 1024 + threadIdx.x;
    const int i = b * NN + q;

    uint r = g_key[i];
    g_key[i] = 0;                                   // self-reset for replay
    float m = unrkey(r);

    const float* p = xyz + (size_t)i * 3;
    float px = p[0], py = p[1], pz = p[2];
    float w = (px*px + py*py) + pz*pz;
    float d2nn = w + m;                             // ||q||^2 + shifted min
    float mself = fmaf(-2.0f*px, px, fmaf(-2.0f*py, py, fmaf(-2.0f*pz, pz, w)));
    float d2self = w + mself;

    float ds = sqrtf(fmaxf(d2self, EPS)) + sqrtf(fmaxf(d2nn, EPS));
    g_dsum[i] = ds;

    float t = reduce1024(ds, sh);
    if (threadIdx.x == 0) atomicAdd(&g_bsum[b], t);
}

// grid (FB, BB) x 1024: threshold (bsum final at kernel boundary), masked sum.
__global__ void __launch_bounds__(1024) k_loss(float* __restrict__ out) {
    __shared__ float sh[32];
    const int b = blockIdx.y;
    const int i = b * NN + blockIdx.x * 1024 + threadIdx.x;

    float thr = (g_bsum[b] / (float)NN) * ALPHA;    // mean, then *ALPHA (ref order)
    float d = g_dsum[i];
    float s = (d > thr) ? d : 0.0f;
    s = reduce1024(s, sh);
    if (threadIdx.x == 0) atomicAdd(out, s);
}

extern "C" void kernel_launch(void* const* d_in, const int* in_sizes, int n_in,
                              void* d_out, int out_size) {
    const float* xyz = (const float*)d_in[0];
    float* out = (float*)d_out;

    dim3 grid(GX, BB, SPLIT);            // 16 x 4 x 64 = 4096 blocks
    k_knn<<<grid, QB>>>(xyz, out);

    dim3 fgrid(FB, BB);                  // 32 wide finish blocks
    k_dsum<<<fgrid, 1024>>>(xyz);
    k_loss<<<fgrid, 1024>>>(out);
}

// round 16
// speedup vs baseline: 1.3520x; 1.1418x over previous
#include <cuda_runtime.h>

#define BB    4
#define NN    8192
#define ALPHA 5.0f
#define EPS   1e-12f

#define SPLIT  64                // ref-dimension split (64 atomics/key max)
#define SLICE  (NN / SPLIT)      // 128 refs per block (2 KB smem)
#define QB     128               // threads per knn block
#define QPT    4                 // queries per thread (2 packed f32x2 lanes)
#define QBLK   (QB * QPT)        // 512 queries per block
#define GX     (NN / QBLK)       // 16 query-groups per batch

#define FB     16                // finish blocks per batch (16*512 = NN)
#define FT     512               // finish threads per block

typedef unsigned long long ull;
typedef unsigned int uint;

// Reversed-order float keys: min over floats == max over keys; 0 = identity.
__device__ uint  g_key [BB * NN];   // zero at load; k_dsum self-resets
__device__ float g_dsum[BB * NN];
__device__ float g_bsum[BB];        // zeroed by k_knn each launch

__device__ __forceinline__ uint rkey(float f) {
    uint b = __float_as_uint(f);
    uint u = (b & 0x80000000u) ? ~b : (b | 0x80000000u);  // ascending order
    return ~u;                                            // descending
}
__device__ __forceinline__ float unrkey(uint r) {
    uint u = ~r;
    uint b = (u & 0x80000000u) ? (u & 0x7FFFFFFFu) : ~u;
    return __uint_as_float(b);
}

__device__ __forceinline__ ull f2u(float a, float b) {
    union { float f[2]; ull u; } t; t.f[0] = a; t.f[1] = b; return t.u;
}
__device__ __forceinline__ void u2f(ull v, float& a, float& b) {
    union { float f[2]; ull u; } t; t.u = v; a = t.f[0]; b = t.f[1];
}
__device__ __forceinline__ ull fma2(ull a, ull b, ull c) {
    ull d; asm("fma.rn.f32x2 %0, %1, %2, %3;" : "=l"(d) : "l"(a), "l"(b), "l"(c)); return d;
}

// Round-12 mainloop (measured best: 39.1us, 40 regs, occ 61%), unroll 8.
// Each block: 512 queries (4/thread, 2 packed f32x2 pairs) vs a 128-ref slice
// in smem as plain float4 (x,y,z,w). One broadcast LDS.128 per ref serves all
// 4 queries. Emits per-query partial min of (w_j - 2*dot_j) via atomicMax(rkey).
__global__ void __launch_bounds__(QB, 10) k_knn(const float* __restrict__ xyz,
                                                float* __restrict__ out) {
    __shared__ float4 sR[SLICE];    // (x, y, z, ||r||^2) per ref

    const int b     = blockIdx.y;
    const int slice = blockIdx.z;
    const int tid   = threadIdx.x;

    // per-replay resets (ordered before k_dsum/k_loss by kernel boundaries)
    if (blockIdx.x == 0 && slice == 0 && tid == 0) {
        if (b == 0) out[0] = 0.0f;
        g_bsum[b] = 0.0f;
    }

    // load this block's ref slice (1 ref per thread; SLICE == QB)
    {
        const float* __restrict__ src = xyz + (size_t)(b * NN + slice * SLICE + tid) * 3;
        float x = src[0], y = src[1], z = src[2];
        float w = (x*x + y*y) + z*z;                 // match jnp.sum order
        sR[tid] = make_float4(x, y, z, w);
    }

    // 4 queries per thread at tid + k*QB; packed as (q0,q1) and (q2,q3)
    const int qbase = blockIdx.x * QBLK + tid;
    ull mx01, my01, mz01, mx23, my23, mz23;
    {
        const float* q0 = xyz + (size_t)(b * NN + qbase + 0 * QB) * 3;
        const float* q1 = xyz + (size_t)(b * NN + qbase + 1 * QB) * 3;
        const float* q2 = xyz + (size_t)(b * NN + qbase + 2 * QB) * 3;
        const float* q3 = xyz + (size_t)(b * NN + qbase + 3 * QB) * 3;
        mx01 = f2u(-2.0f*q0[0], -2.0f*q1[0]);
        my01 = f2u(-2.0f*q0[1], -2.0f*q1[1]);
        mz01 = f2u(-2.0f*q0[2], -2.0f*q1[2]);
        mx23 = f2u(-2.0f*q2[0], -2.0f*q3[0]);
        my23 = f2u(-2.0f*q2[1], -2.0f*q3[1]);
        mz23 = f2u(-2.0f*q2[2], -2.0f*q3[2]);
    }

    __syncthreads();

    const bool self_block = ((slice >> 2) == blockIdx.x);  // QBLK == 4*SLICE
    float part[QPT];

    if (!self_block) {
        // fast path: plain min, 4 independent accumulators, deep unroll for ILP
        float a0 = 3.4e38f, a1 = 3.4e38f, a2 = 3.4e38f, a3 = 3.4e38f;

        #pragma unroll 8
        for (int j = 0; j < SLICE; j++) {
            float4 R = sR[j];
            ull xx = f2u(R.x, R.x), yy = f2u(R.y, R.y);
            ull zz = f2u(R.z, R.z), ww = f2u(R.w, R.w);
            ull t01 = fma2(mx01, xx, fma2(my01, yy, fma2(mz01, zz, ww)));
            ull t23 = fma2(mx23, xx, fma2(my23, yy, fma2(mz23, zz, ww)));
            float c0, c1, c2, c3;
            u2f(t01, c0, c1); u2f(t23, c2, c3);
            a0 = fminf(a0, c0);
            a1 = fminf(a1, c1);
            a2 = fminf(a2, c2);
            a3 = fminf(a3, c3);
        }
        part[0] = a0; part[1] = a1; part[2] = a2; part[3] = a3;
    } else {
        // self path: 2-min per query; group (slice&3) gets second smallest
        float s0[QPT], s1[QPT];
        #pragma unroll
        for (int k = 0; k < QPT; k++) { s0[k] = 3.4e38f; s1[k] = 3.4e38f; }

        #pragma unroll 2
        for (int j = 0; j < SLICE; j++) {
            float4 R = sR[j];
            ull xx = f2u(R.x, R.x), yy = f2u(R.y, R.y);
            ull zz = f2u(R.z, R.z), ww = f2u(R.w, R.w);
            ull t01 = fma2(mx01, xx, fma2(my01, yy, fma2(mz01, zz, ww)));
            ull t23 = fma2(mx23, xx, fma2(my23, yy, fma2(mz23, zz, ww)));
            float c[QPT];
            u2f(t01, c[0], c[1]); u2f(t23, c[2], c[3]);
            #pragma unroll
            for (int k = 0; k < QPT; k++) {
                float hi = fmaxf(s0[k], c[k]);
                s0[k] = fminf(s0[k], c[k]);
                s1[k] = fminf(s1[k], hi);
            }
        }
        const int special = slice & 3;               // group whose selves are here
        #pragma unroll
        for (int k = 0; k < QPT; k++)
            part[k] = (k == special) ? s1[k] : s0[k];
    }

    #pragma unroll
    for (int k = 0; k < QPT; k++)
        atomicMax(&g_key[b * NN + qbase + k * QB], rkey(part[k]));
}

__device__ __forceinline__ float reduce_block(float v, float* sh) {
    int lane = threadIdx.x & 31, wid = threadIdx.x >> 5;
    #pragma unroll
    for (int o = 16; o; o >>= 1) v += __shfl_down_sync(0xFFFFFFFFu, v, o);
    if (lane == 0) sh[wid] = v;
    __syncthreads();
    int nw = blockDim.x >> 5;
    if (wid == 0) {
        v = (lane < nw) ? sh[lane] : 0.0f;
        #pragma unroll
        for (int o = 8; o; o >>= 1) v += __shfl_down_sync(0xFFFFFFFFu, v, o);
    }
    return v;   // valid in thread 0 (for blockDim <= 512)
}

// grid (FB, BB) x FT: one point/thread. Decode key (+reset), dsum, batch sum.
__global__ void __launch_bounds__(FT) k_dsum(const float* __restrict__ xyz) {
    __shared__ float sh[16];
    const int b = blockIdx.y;
    const int q = blockIdx.x * FT + threadIdx.x;
    const int i = b * NN + q;

    uint r = g_key[i];
    g_key[i] = 0;                                   // self-reset for replay
    float m = unrkey(r);

    const float* p = xyz + (size_t)i * 3;
    float px = p[0], py = p[1], pz = p[2];
    float w = (px*px + py*py) + pz*pz;
    float d2nn = w + m;                             // ||q||^2 + shifted min
    float mself = fmaf(-2.0f*px, px, fmaf(-2.0f*py, py, fmaf(-2.0f*pz, pz, w)));
    float d2self = w + mself;

    float ds = sqrtf(fmaxf(d2self, EPS)) + sqrtf(fmaxf(d2nn, EPS));
    g_dsum[i] = ds;

    float t = reduce_block(ds, sh);
    if (threadIdx.x == 0) atomicAdd(&g_bsum[b], t);
}

// grid (FB, BB) x FT: threshold (bsum final at kernel boundary), masked sum.
__global__ void __launch_bounds__(FT) k_loss(float* __restrict__ out) {
    __shared__ float sh[16];
    const int b = blockIdx.y;
    const int i = b * NN + blockIdx.x * FT + threadIdx.x;

    float thr = (g_bsum[b] / (float)NN) * ALPHA;    // mean, then *ALPHA (ref order)
    float d = g_dsum[i];
    float s = (d > thr) ? d : 0.0f;
    s = reduce_block(s, sh);
    if (threadIdx.x == 0) atomicAdd(out, s);
}

extern "C" void kernel_launch(void* const* d_in, const int* in_sizes, int n_in,
                              void* d_out, int out_size) {
    const float* xyz = (const float*)d_in[0];
    float* out = (float*)d_out;

    dim3 grid(GX, BB, SPLIT);            // 16 x 4 x 64 = 4096 blocks
    k_knn<<<grid, QB>>>(xyz, out);

    dim3 fgrid(FB, BB);                  // 64 finish blocks
    k_dsum<<<fgrid, FT>>>(xyz);
    k_loss<<<fgrid, FT>>>(out);
}